// round 1
// baseline (speedup 1.0000x reference)
#include <cuda_runtime.h>
#include <cuda_bf16.h>

#define EPS 0.1f
#define NTHREADS 256

// Stable, fast log-sigmoid: logsig(x) = min(x,0) - log(1 + exp(-|x|))
// 2 MUFU ops (EX2 + LG2) per element via fast intrinsics.
__device__ __forceinline__ float logsig(float x) {
    float e = __expf(-fabsf(x));
    float l = __logf(1.0f + e);
    return fminf(x, 0.0f) - l;
}

__global__ __launch_bounds__(NTHREADS) void ls_loss_kernel(
    const float* __restrict__ output,
    const int*   __restrict__ label,
    const int*   __restrict__ test_label,
    float*       __restrict__ out,
    int num_type, int L)
{
    const int b   = blockIdx.x;
    const int tid = threadIdx.x;
    const int twoL = 2 * L;

    __shared__ int   lab[128];             // 2*L = 100 candidate labels
    __shared__ float warpsum[NTHREADS / 32];

    if (tid < L)           lab[tid] = label[b * L + tid];
    else if (tid < twoL)   lab[tid] = test_label[b * L + (tid - L)];
    __syncthreads();

    const float c0 = EPS / (float)num_type;
    const float* row = output + (size_t)b * (size_t)num_type;

    // ---- dense part: S = sum_n logsig(row[n]), float4 coalesced stream ----
    float s = 0.0f;
    const int nvec = num_type >> 2;
    const float4* rowv = (const float4*)row;
    #pragma unroll 4
    for (int i = tid; i < nvec; i += NTHREADS) {
        float4 v = __ldg(rowv + i);
        s += logsig(v.x);
        s += logsig(v.y);
        s += logsig(v.z);
        s += logsig(v.w);
    }
    // scalar tail (num_type % 4 == 0 for this problem; kept for safety)
    for (int i = (nvec << 2) + tid; i < num_type; i += NTHREADS)
        s += logsig(row[i]);

    float acc = s * c0;

    // ---- sparse corrections with set semantics (dedup + test-overwrites-label) ----
    if (tid < twoL) {
        int raw = lab[tid];
        if (raw != 0) {                      // raw==0 means padding (dropped)
            int j = raw - 1;                 // valid: raw in [1, num_type]
            bool canon = true;
            if (tid >= L) {
                // test entry: canonical if first occurrence within the test list
                for (int k = L; k < tid; k++)
                    if (lab[k] == raw) { canon = false; break; }
                if (canon)
                    acc += (2.0f * (1.0f - EPS) - 2.0f * c0) * logsig(row[j]);
            } else {
                // label entry: canonical if first occurrence in label list
                // AND not present anywhere in the test list (test overwrites)
                for (int k = 0; k < tid; k++)
                    if (lab[k] == raw) { canon = false; break; }
                if (canon)
                    for (int k = L; k < twoL; k++)
                        if (lab[k] == raw) { canon = false; break; }
                if (canon)
                    acc += ((1.0f - EPS) - c0) * logsig(row[j]);
            }
        }
    }

    // ---- block reduction ----
    #pragma unroll
    for (int o = 16; o > 0; o >>= 1)
        acc += __shfl_down_sync(0xffffffffu, acc, o);
    if ((tid & 31) == 0) warpsum[tid >> 5] = acc;
    __syncthreads();

    if (tid < NTHREADS / 32) {
        float v = warpsum[tid];
        #pragma unroll
        for (int o = NTHREADS / 64; o > 0; o >>= 1)
            v += __shfl_down_sync(0xffu, v, o);
        if (tid == 0) out[b] = -v;
    }
}

extern "C" void kernel_launch(void* const* d_in, const int* in_sizes, int n_in,
                              void* d_out, int out_size)
{
    const float* output     = (const float*)d_in[0];
    const int*   label      = (const int*)d_in[1];
    const int*   test_label = (const int*)d_in[2];
    float*       out        = (float*)d_out;

    const int B        = out_size;               // 4096
    const int num_type = in_sizes[0] / B;        // 32000
    const int L        = in_sizes[1] / B;        // 50

    ls_loss_kernel<<<B, NTHREADS>>>(output, label, test_label, out, num_type, L);
}